// round 13
// baseline (speedup 1.0000x reference)
#include <cuda_runtime.h>
#include <cuda_fp16.h>
#include <cstdint>

#define RES   128
#define FEAT  32
#define NVOX  (RES * RES * RES)           // 2,097,152 voxels
#define NPTS  (2048 * 1024)               // 2,097,152 points
#define FULLM 0xffffffffu

// fp16 voxel tensor holding layer-1 pre-activations: vox[v*32+j] = (W1 @ g[:,v])[j]
__device__ __half g_vox16[(size_t)NVOX * FEAT];
// Split-fp16 B-fragments: W1 (0..7), W2 (8..15), W3 (16..23), W4 (24..25).
// Per lane: {hi_b0, hi_b1, lo_b0, lo_b1}.
__device__ uint4 g_whalf[26 * 32];

// ---------------------------------------------------------------------------
__device__ __forceinline__ void mma_f16(float d[4],
                                        uint32_t a0, uint32_t a1, uint32_t a2, uint32_t a3,
                                        uint32_t b0, uint32_t b1) {
    asm volatile("mma.sync.aligned.m16n8k16.row.col.f32.f16.f16.f32 "
                 "{%0,%1,%2,%3}, {%4,%5,%6,%7}, {%8,%9}, {%0,%1,%2,%3};"
                 : "+f"(d[0]), "+f"(d[1]), "+f"(d[2]), "+f"(d[3])
                 : "r"(a0), "r"(a1), "r"(a2), "r"(a3), "r"(b0), "r"(b1));
}

// hi/lo fp16 split of a float pair (packed f16x2 each)
__device__ __forceinline__ void hilo2(float x, float y, uint32_t& hi, uint32_t& lo) {
    const __half2 h = __floats2half2_rn(x, y);
    hi = *(const uint32_t*)&h;
    const float2 hf = __half22float2(h);
    const __half2 l = __floats2half2_rn(x - hf.x, y - hf.y);
    lo = *(const uint32_t*)&l;
}

// relu, then hi/lo split
__device__ __forceinline__ void prelu_hilo2(float x, float y, uint32_t& hi, uint32_t& lo) {
    hilo2(fmaxf(x, 0.0f), fmaxf(y, 0.0f), hi, lo);
}

// ---------------------------------------------------------------------------
// Prep (single kernel): split-fp16 B-fragments for all layers, m16n8k16 order.
// ---------------------------------------------------------------------------
__global__ void prep_whalf_kernel(const float* __restrict__ w1, const float* __restrict__ w2,
                                  const float* __restrict__ w3, const float* __restrict__ w4) {
    const int f = blockIdx.x;        // 0..25
    const int lane = threadIdx.x;
    const int g = lane >> 2, t = lane & 3;
    float v0 = 0.f, v1 = 0.f, v2 = 0.f, v3 = 0.f;
    if (f < 24) {
        const float* W = (f < 8) ? w1 : (f < 16) ? w2 : w3;
        const int r = f & 7, ks = r >> 2, nt = r & 3;
        const int row = 8 * nt + g, k = 16 * ks;
        v0 = W[row * 32 + k + 2 * t];
        v1 = W[row * 32 + k + 2 * t + 1];
        v2 = W[row * 32 + k + 2 * t + 8];
        v3 = W[row * 32 + k + 2 * t + 9];
    } else {
        const int ks = f - 24;
        if (g < 4) {
            v0 = w4[g * 32 + 16 * ks + 2 * t];
            v1 = w4[g * 32 + 16 * ks + 2 * t + 1];
            v2 = w4[g * 32 + 16 * ks + 2 * t + 8];
            v3 = w4[g * 32 + 16 * ks + 2 * t + 9];
        }
    }
    uint4 u;
    hilo2(v0, v1, u.x, u.z);
    hilo2(v2, v3, u.y, u.w);
    g_whalf[f * 32 + lane] = u;
}

// ---------------------------------------------------------------------------
// Voxel transform: grid (C,D,H,W) -> fp16 (D*H*W, 32) of W1 @ v.
// fp16 hi/lo split mma. (DRAM-floored at ~402 MB streamed.)
// ---------------------------------------------------------------------------
#define TC_STRIDE 260
__global__ void __launch_bounds__(256, 4) voxel_w1_kernel(const float* __restrict__ g) {
    __shared__ float tile[32 * TC_STRIDE];     // 33,280 B  (c-major)
    __shared__ uint4 swh1[8 * 32];             //  4,096 B  (W1 frags)
    const int tid = threadIdx.x;
    const int v0 = blockIdx.x * 256;

    for (int i = tid; i < 8 * 32; i += 256) swh1[i] = g_whalf[i];

#pragma unroll
    for (int i = 0; i < 8; i++) {
        const int idx = tid + i * 256;
        const int c = idx >> 6, v4 = idx & 63;
        const float4 val = *(const float4*)&g[(size_t)c * NVOX + v0 + v4 * 4];
        *(float4*)&tile[c * TC_STRIDE + v4 * 4] = val;
    }
    __syncthreads();

    const int warp = tid >> 5, lane = tid & 31;
    const int gq = lane >> 2, t = lane & 3;
    const int vb = warp * 32;

#pragma unroll
    for (int mt = 0; mt < 2; mt++) {
        const int r = vb + 16 * mt + gq;
        float D[4][4];
#pragma unroll
        for (int nt = 0; nt < 4; nt++)
#pragma unroll
            for (int i = 0; i < 4; i++) D[nt][i] = 0.0f;

#pragma unroll
        for (int ks = 0; ks < 2; ks++) {
            const int k = 16 * ks + 2 * t;
            uint32_t a0h, a0l, a1h, a1l, a2h, a2l, a3h, a3l;
            hilo2(tile[k * TC_STRIDE + r],           tile[(k + 1) * TC_STRIDE + r],     a0h, a0l);
            hilo2(tile[k * TC_STRIDE + r + 8],       tile[(k + 1) * TC_STRIDE + r + 8], a1h, a1l);
            hilo2(tile[(k + 8) * TC_STRIDE + r],     tile[(k + 9) * TC_STRIDE + r],     a2h, a2l);
            hilo2(tile[(k + 8) * TC_STRIDE + r + 8], tile[(k + 9) * TC_STRIDE + r + 8], a3h, a3l);
#pragma unroll
            for (int nt = 0; nt < 4; nt++) {
                const uint4 B = swh1[(ks * 4 + nt) * 32 + lane];
                mma_f16(D[nt], a0h, a1h, a2h, a3h, B.x, B.y);
                mma_f16(D[nt], a0l, a1l, a2l, a3l, B.x, B.y);
                mma_f16(D[nt], a0h, a1h, a2h, a3h, B.z, B.w);
            }
        }
#pragma unroll
        for (int nt = 0; nt < 4; nt++) {
            const int v = v0 + vb + 16 * mt + gq;
            const __half2 p0 = __floats2half2_rn(D[nt][0], D[nt][1]);
            const __half2 p1 = __floats2half2_rn(D[nt][2], D[nt][3]);
            *(__half2*)&g_vox16[(size_t)v * 32 + 8 * nt + 2 * t]       = p0;
            *(__half2*)&g_vox16[(size_t)(v + 8) * 32 + 8 * nt + 2 * t] = p1;
        }
    }
}

// ---------------------------------------------------------------------------
// Fused gather + 3 MLP layers (fp16 mma, hi/lo split operands).
// Gather re-layout: 8 lanes per point (x-corner side || 16B chunk),
// 4 points/round x 8 rounds. One LDG.128 covers BOTH x-corners of a point
// (same 128B line when x0 even -> ~25% fewer gather wavefronts); the two
// x-side partial sums combine via shfl_xor(4). Side0 lanes store hi, side1
// store lo -> svu STS.128 is bank-conflict-free.
// ---------------------------------------------------------------------------
#define SV_STRIDE 36   // uints per point: 16 hi + 16 lo + 4 pad

__global__ void __launch_bounds__(256, 3) fused_field_kernel(
    const float* __restrict__ coord,
    const float* __restrict__ b1g, const float* __restrict__ b2g,
    const float* __restrict__ b3g, const float* __restrict__ b4g,
    float* __restrict__ out)
{
    __shared__ uint4 swh[26 * 32];             // 13,312 B
    __shared__ float sb[128];                  //    512 B
    __shared__ uint32_t svu[256 * SV_STRIDE];  // 36,864 B

    const int tid = threadIdx.x;
    {
        for (int i = tid; i < 26 * 32; i += 256) swh[i] = g_whalf[i];
        if (tid < 32) {
            sb[tid]      = b1g[tid];
            sb[32 + tid] = b2g[tid];
            sb[64 + tid] = b3g[tid];
            sb[96 + tid] = (tid < 4) ? b4g[tid] : 0.0f;
        }
    }
    __syncthreads();

    const int warp  = tid >> 5;
    const int lane  = tid & 31;
    const int psub  = lane >> 3;       // point-of-4 in round
    const int side  = (lane >> 2) & 1; // which x-corner this lane covers
    const int chunk = lane & 3;        // 16B chunk (8 channels) within voxel

    float bb[8];
#pragma unroll
    for (int i = 0; i < 8; i++) bb[i] = sb[8 * chunk + i];   // b1 slice

    // --- Phase 1: gather in two halves of 4 rounds (bounded coord regs) ---
#pragma unroll
    for (int h = 0; h < 2; h++) {
        float cr[4][3];
#pragma unroll
        for (int s2 = 0; s2 < 4; s2++) {
            const int q   = (warp << 5) + ((h * 4 + s2) << 2) + psub;
            const int pid = blockIdx.x * 256 + q;
            cr[s2][0] = __ldg(&coord[pid * 3 + 0]);
            cr[s2][1] = __ldg(&coord[pid * 3 + 1]);
            cr[s2][2] = __ldg(&coord[pid * 3 + 2]);
        }

#pragma unroll
        for (int s2 = 0; s2 < 4; s2++) {
            const int q = (warp << 5) + ((h * 4 + s2) << 2) + psub;

            const float fx = (cr[s2][0] + 1.0f) * 64.0f - 0.5f;
            const float fy = (cr[s2][1] + 1.0f) * 64.0f - 0.5f;
            const float fz = (cr[s2][2] + 1.0f) * 64.0f - 0.5f;

            const float x0f = floorf(fx), y0f = floorf(fy), z0f = floorf(fz);
            const float tx = fx - x0f, ty = fy - y0f, tz = fz - z0f;
            const int x0 = (int)x0f, y0 = (int)y0f, z0 = (int)z0f;

            int   ys[2], zs[2];
            float wy[2], wz[2];
            ys[0] = max(y0, 0);        ys[1] = min(y0 + 1, RES - 1);
            zs[0] = max(z0, 0);        zs[1] = min(z0 + 1, RES - 1);
            wy[0] = (y0 >= 0)          ? (1.0f - ty) : 0.0f;
            wy[1] = (y0 + 1 <= RES - 1)? ty          : 0.0f;
            wz[0] = (z0 >= 0)          ? (1.0f - tz) : 0.0f;
            wz[1] = (z0 + 1 <= RES - 1)? tz          : 0.0f;

            // this lane's x-side
            int   xv;
            float wxs;
            if (side == 0) { xv = max(x0, 0);           wxs = (x0 >= 0)           ? (1.0f - tx) : 0.0f; }
            else           { xv = min(x0 + 1, RES - 1); wxs = (x0 + 1 <= RES - 1) ? tx          : 0.0f; }

            // one LDG.128 per (kz,ky): both x-corners of 4 points per instr
            uint4 raw[4];
            float w4c[4];
#pragma unroll
            for (int c = 0; c < 4; c++) {
                const int kz = c >> 1, ky = c & 1;
                const int vox = ((zs[kz] * RES + ys[ky]) * RES + xv);
                raw[c] = __ldg(((const uint4*)(g_vox16 + ((size_t)vox << 5))) + chunk);
                w4c[c] = wz[kz] * wy[ky] * wxs;
            }

            float acc[8];
#pragma unroll
            for (int i = 0; i < 8; i++) acc[i] = 0.0f;
#pragma unroll
            for (int c = 0; c < 4; c++) {
                const __half2* h2 = (const __half2*)&raw[c];
                const float2 f0 = __half22float2(h2[0]);
                const float2 f1 = __half22float2(h2[1]);
                const float2 f2 = __half22float2(h2[2]);
                const float2 f3 = __half22float2(h2[3]);
                const float w = w4c[c];
                acc[0] = fmaf(w, f0.x, acc[0]);  acc[1] = fmaf(w, f0.y, acc[1]);
                acc[2] = fmaf(w, f1.x, acc[2]);  acc[3] = fmaf(w, f1.y, acc[3]);
                acc[4] = fmaf(w, f2.x, acc[4]);  acc[5] = fmaf(w, f2.y, acc[5]);
                acc[6] = fmaf(w, f3.x, acc[6]);  acc[7] = fmaf(w, f3.y, acc[7]);
            }

            // combine the two x-sides (partner lane = lane ^ 4), add bias
#pragma unroll
            for (int i = 0; i < 8; i++) {
                acc[i] += __shfl_xor_sync(FULLM, acc[i], 4);
                acc[i] += bb[i];
            }

            uint4 hi, lo;
            prelu_hilo2(acc[0], acc[1], hi.x, lo.x);
            prelu_hilo2(acc[2], acc[3], hi.y, lo.y);
            prelu_hilo2(acc[4], acc[5], hi.z, lo.z);
            prelu_hilo2(acc[6], acc[7], hi.w, lo.w);

            // side0 -> hi block, side1 -> lo block (conflict-free STS.128)
            const int base = q * SV_STRIDE + side * 16 + 4 * chunk;
            *(uint4*)&svu[base] = side ? lo : hi;
        }
    }
    __syncwarp();

    // --- Phase 2: layers 2..4, one m-tile at a time ---
    const int gq = lane >> 2, t = lane & 3;

#pragma unroll
    for (int mt = 0; mt < 2; mt++) {
        const int q0 = warp * 32 + 16 * mt + gq;

        // layer 2: A = svu hi/lo, B = W2 frags 8..15, init b2
        float D[4][4];
#pragma unroll
        for (int nt = 0; nt < 4; nt++) {
            const float2 b2v = *(const float2*)&sb[32 + 8 * nt + 2 * t];
            D[nt][0] = b2v.x; D[nt][1] = b2v.y;
            D[nt][2] = b2v.x; D[nt][3] = b2v.y;
        }
#pragma unroll
        for (int ks = 0; ks < 2; ks++) {
            const uint32_t a0h = svu[q0 * SV_STRIDE + 8 * ks + t];
            const uint32_t a1h = svu[(q0 + 8) * SV_STRIDE + 8 * ks + t];
            const uint32_t a2h = svu[q0 * SV_STRIDE + 8 * ks + t + 4];
            const uint32_t a3h = svu[(q0 + 8) * SV_STRIDE + 8 * ks + t + 4];
            const uint32_t a0l = svu[q0 * SV_STRIDE + 16 + 8 * ks + t];
            const uint32_t a1l = svu[(q0 + 8) * SV_STRIDE + 16 + 8 * ks + t];
            const uint32_t a2l = svu[q0 * SV_STRIDE + 16 + 8 * ks + t + 4];
            const uint32_t a3l = svu[(q0 + 8) * SV_STRIDE + 16 + 8 * ks + t + 4];
#pragma unroll
            for (int nt = 0; nt < 4; nt++) {
                const uint4 B = swh[(8 + ks * 4 + nt) * 32 + lane];
                mma_f16(D[nt], a0h, a1h, a2h, a3h, B.x, B.y);
                mma_f16(D[nt], a0l, a1l, a2l, a3l, B.x, B.y);
                mma_f16(D[nt], a0h, a1h, a2h, a3h, B.z, B.w);
            }
        }

        // layer 3: A = relu(D) hi/lo, B = W3 frags 16..23, init b3
        float Dn[4][4];
#pragma unroll
        for (int nt = 0; nt < 4; nt++) {
            const float2 b3v = *(const float2*)&sb[64 + 8 * nt + 2 * t];
            Dn[nt][0] = b3v.x; Dn[nt][1] = b3v.y;
            Dn[nt][2] = b3v.x; Dn[nt][3] = b3v.y;
        }
#pragma unroll
        for (int ks = 0; ks < 2; ks++) {
            uint32_t a0h, a1h, a2h, a3h, a0l, a1l, a2l, a3l;
            prelu_hilo2(D[2 * ks][0],     D[2 * ks][1],     a0h, a0l);
            prelu_hilo2(D[2 * ks][2],     D[2 * ks][3],     a1h, a1l);
            prelu_hilo2(D[2 * ks + 1][0], D[2 * ks + 1][1], a2h, a2l);
            prelu_hilo2(D[2 * ks + 1][2], D[2 * ks + 1][3], a3h, a3l);
#pragma unroll
            for (int nt = 0; nt < 4; nt++) {
                const uint4 B = swh[(16 + ks * 4 + nt) * 32 + lane];
                mma_f16(Dn[nt], a0h, a1h, a2h, a3h, B.x, B.y);
                mma_f16(Dn[nt], a0l, a1l, a2l, a3l, B.x, B.y);
                mma_f16(Dn[nt], a0h, a1h, a2h, a3h, B.z, B.w);
            }
        }

        // layer 4: A = relu(Dn) hi/lo, B = W4 frags 24..25, init b4, no relu
        float O[4];
        {
            const float2 b4v = *(const float2*)&sb[96 + 2 * t];
            O[0] = b4v.x; O[1] = b4v.y;
            O[2] = b4v.x; O[3] = b4v.y;
        }
#pragma unroll
        for (int ks = 0; ks < 2; ks++) {
            uint32_t a0h, a1h, a2h, a3h, a0l, a1l, a2l, a3l;
            prelu_hilo2(Dn[2 * ks][0],     Dn[2 * ks][1],     a0h, a0l);
            prelu_hilo2(Dn[2 * ks][2],     Dn[2 * ks][3],     a1h, a1l);
            prelu_hilo2(Dn[2 * ks + 1][0], Dn[2 * ks + 1][1], a2h, a2l);
            prelu_hilo2(Dn[2 * ks + 1][2], Dn[2 * ks + 1][3], a3h, a3l);
            const uint4 B = swh[(24 + ks) * 32 + lane];
            mma_f16(O, a0h, a1h, a2h, a3h, B.x, B.y);
            mma_f16(O, a0l, a1l, a2l, a3l, B.x, B.y);
            mma_f16(O, a0h, a1h, a2h, a3h, B.z, B.w);
        }

        // store: rows gq, gq+8 of this m-tile, cols 2t,2t+1 (valid cols < 4)
        if (t < 2) {
            const int p0 = blockIdx.x * 256 + warp * 32 + 16 * mt + gq;
            *(float2*)&out[p0 * 4 + 2 * t]       = make_float2(O[0], O[1]);
            *(float2*)&out[(p0 + 8) * 4 + 2 * t] = make_float2(O[2], O[3]);
        }
    }
}

// ---------------------------------------------------------------------------
extern "C" void kernel_launch(void* const* d_in, const int* in_sizes, int n_in,
                              void* d_out, int out_size)
{
    const float* coord = (const float*)d_in[0];
    const float* grid  = (const float*)d_in[1];
    const float* w1 = (const float*)d_in[2];
    const float* b1 = (const float*)d_in[3];
    const float* w2 = (const float*)d_in[4];
    const float* b2 = (const float*)d_in[5];
    const float* w3 = (const float*)d_in[6];
    const float* b3 = (const float*)d_in[7];
    const float* w4 = (const float*)d_in[8];
    const float* b4 = (const float*)d_in[9];
    float* out = (float*)d_out;

    cudaFuncSetAttribute(fused_field_kernel,
                         cudaFuncAttributePreferredSharedMemoryCarveout, 62);

    prep_whalf_kernel<<<26, 32>>>(w1, w2, w3, w4);
    voxel_w1_kernel<<<NVOX / 256, 256>>>(grid);
    fused_field_kernel<<<NPTS / 256, 256>>>(coord, b1, b2, b3, b4, out);
}

// round 16
// speedup vs baseline: 1.0622x; 1.0622x over previous
#include <cuda_runtime.h>
#include <cuda_fp16.h>
#include <cstdint>

#define RES   128
#define FEAT  32
#define NVOX  (RES * RES * RES)           // 2,097,152 voxels
#define NPTS  (2048 * 1024)               // 2,097,152 points

// fp16 voxel tensor holding layer-1 pre-activations: vox[v*32+j] = (W1 @ g[:,v])[j]
__device__ __half g_vox16[(size_t)NVOX * FEAT];
// Split-fp16 B-fragments: W1 (0..7), W2 (8..15), W3 (16..23), W4 (24..25).
// Per lane: {hi_b0, hi_b1, lo_b0, lo_b1}.
__device__ uint4 g_whalf[26 * 32];

// ---------------------------------------------------------------------------
__device__ __forceinline__ void mma_f16(float d[4],
                                        uint32_t a0, uint32_t a1, uint32_t a2, uint32_t a3,
                                        uint32_t b0, uint32_t b1) {
    asm volatile("mma.sync.aligned.m16n8k16.row.col.f32.f16.f16.f32 "
                 "{%0,%1,%2,%3}, {%4,%5,%6,%7}, {%8,%9}, {%0,%1,%2,%3};"
                 : "+f"(d[0]), "+f"(d[1]), "+f"(d[2]), "+f"(d[3])
                 : "r"(a0), "r"(a1), "r"(a2), "r"(a3), "r"(b0), "r"(b1));
}

// L2 eviction hints — sm_103a ptxas rejects direct .L2::evict_* modifiers on
// anything narrower than 256-bit loads; the createpolicy + cache_hint operand
// form works for all widths. ALL hinted loads go through cache_hint.
__device__ __forceinline__ uint64_t policy_evict_last() {
    uint64_t p;
    asm("createpolicy.fractional.L2::evict_last.b64 %0, 1.0;" : "=l"(p));
    return p;
}
__device__ __forceinline__ uint64_t policy_evict_first() {
    uint64_t p;
    asm("createpolicy.fractional.L2::evict_first.b64 %0, 1.0;" : "=l"(p));
    return p;
}
__device__ __forceinline__ uint4 ldg_hint_v4u(const void* p, uint64_t pol) {
    uint4 v;
    asm volatile("ld.global.nc.L2::cache_hint.v4.u32 {%0,%1,%2,%3}, [%4], %5;"
                 : "=r"(v.x), "=r"(v.y), "=r"(v.z), "=r"(v.w) : "l"(p), "l"(pol));
    return v;
}
__device__ __forceinline__ float ldg_hint_f32(const float* p, uint64_t pol) {
    float v;
    asm volatile("ld.global.nc.L2::cache_hint.f32 %0, [%1], %2;"
                 : "=f"(v) : "l"(p), "l"(pol));
    return v;
}
__device__ __forceinline__ float4 ldg_hint_v4f(const float* p, uint64_t pol) {
    float4 v;
    asm volatile("ld.global.nc.L2::cache_hint.v4.f32 {%0,%1,%2,%3}, [%4], %5;"
                 : "=f"(v.x), "=f"(v.y), "=f"(v.z), "=f"(v.w) : "l"(p), "l"(pol));
    return v;
}
__device__ __forceinline__ void stg_cs_v2f(float* p, float a, float b) {
    asm volatile("st.global.cs.v2.f32 [%0], {%1,%2};" :: "l"(p), "f"(a), "f"(b) : "memory");
}

// hi/lo fp16 split of a float pair (packed f16x2 each)
__device__ __forceinline__ void hilo2(float x, float y, uint32_t& hi, uint32_t& lo) {
    const __half2 h = __floats2half2_rn(x, y);
    hi = *(const uint32_t*)&h;
    const float2 hf = __half22float2(h);
    const __half2 l = __floats2half2_rn(x - hf.x, y - hf.y);
    lo = *(const uint32_t*)&l;
}

// relu, then hi/lo split
__device__ __forceinline__ void prelu_hilo2(float x, float y, uint32_t& hi, uint32_t& lo) {
    hilo2(fmaxf(x, 0.0f), fmaxf(y, 0.0f), hi, lo);
}

// ---------------------------------------------------------------------------
// Prep (single kernel): split-fp16 B-fragments for all layers, m16n8k16 order.
// ---------------------------------------------------------------------------
__global__ void prep_whalf_kernel(const float* __restrict__ w1, const float* __restrict__ w2,
                                  const float* __restrict__ w3, const float* __restrict__ w4) {
    const int f = blockIdx.x;        // 0..25
    const int lane = threadIdx.x;
    const int g = lane >> 2, t = lane & 3;
    float v0 = 0.f, v1 = 0.f, v2 = 0.f, v3 = 0.f;
    if (f < 24) {
        const float* W = (f < 8) ? w1 : (f < 16) ? w2 : w3;
        const int r = f & 7, ks = r >> 2, nt = r & 3;
        const int row = 8 * nt + g, k = 16 * ks;
        v0 = W[row * 32 + k + 2 * t];
        v1 = W[row * 32 + k + 2 * t + 1];
        v2 = W[row * 32 + k + 2 * t + 8];
        v3 = W[row * 32 + k + 2 * t + 9];
    } else {
        const int ks = f - 24;
        if (g < 4) {
            v0 = w4[g * 32 + 16 * ks + 2 * t];
            v1 = w4[g * 32 + 16 * ks + 2 * t + 1];
            v2 = w4[g * 32 + 16 * ks + 2 * t + 8];
            v3 = w4[g * 32 + 16 * ks + 2 * t + 9];
        }
    }
    uint4 u;
    hilo2(v0, v1, u.x, u.z);
    hilo2(v2, v3, u.y, u.w);
    g_whalf[f * 32 + lane] = u;
}

// ---------------------------------------------------------------------------
// Voxel transform: grid (C,D,H,W) -> fp16 (D*H*W, 32) of W1 @ v.
// Grid reads are a pure stream -> evict_first policy so they don't displace
// the voxel tensor the fused kernel will gather from.
// ---------------------------------------------------------------------------
#define TC_STRIDE 260
__global__ void __launch_bounds__(256, 4) voxel_w1_kernel(const float* __restrict__ g) {
    __shared__ float tile[32 * TC_STRIDE];     // 33,280 B  (c-major)
    __shared__ uint4 swh1[8 * 32];             //  4,096 B  (W1 frags)
    const int tid = threadIdx.x;
    const int v0 = blockIdx.x * 256;

    for (int i = tid; i < 8 * 32; i += 256) swh1[i] = g_whalf[i];

    const uint64_t polf = policy_evict_first();
#pragma unroll
    for (int i = 0; i < 8; i++) {
        const int idx = tid + i * 256;
        const int c = idx >> 6, v4 = idx & 63;
        const float4 val = ldg_hint_v4f(&g[(size_t)c * NVOX + v0 + v4 * 4], polf);
        *(float4*)&tile[c * TC_STRIDE + v4 * 4] = val;
    }
    __syncthreads();

    const int warp = tid >> 5, lane = tid & 31;
    const int gq = lane >> 2, t = lane & 3;
    const int vb = warp * 32;

#pragma unroll
    for (int mt = 0; mt < 2; mt++) {
        const int r = vb + 16 * mt + gq;
        float D[4][4];
#pragma unroll
        for (int nt = 0; nt < 4; nt++)
#pragma unroll
            for (int i = 0; i < 4; i++) D[nt][i] = 0.0f;

#pragma unroll
        for (int ks = 0; ks < 2; ks++) {
            const int k = 16 * ks + 2 * t;
            uint32_t a0h, a0l, a1h, a1l, a2h, a2l, a3h, a3l;
            hilo2(tile[k * TC_STRIDE + r],           tile[(k + 1) * TC_STRIDE + r],     a0h, a0l);
            hilo2(tile[k * TC_STRIDE + r + 8],       tile[(k + 1) * TC_STRIDE + r + 8], a1h, a1l);
            hilo2(tile[(k + 8) * TC_STRIDE + r],     tile[(k + 9) * TC_STRIDE + r],     a2h, a2l);
            hilo2(tile[(k + 8) * TC_STRIDE + r + 8], tile[(k + 9) * TC_STRIDE + r + 8], a3h, a3l);
#pragma unroll
            for (int nt = 0; nt < 4; nt++) {
                const uint4 B = swh1[(ks * 4 + nt) * 32 + lane];
                mma_f16(D[nt], a0h, a1h, a2h, a3h, B.x, B.y);
                mma_f16(D[nt], a0l, a1l, a2l, a3l, B.x, B.y);
                mma_f16(D[nt], a0h, a1h, a2h, a3h, B.z, B.w);
            }
        }
#pragma unroll
        for (int nt = 0; nt < 4; nt++) {
            const int v = v0 + vb + 16 * mt + gq;
            const __half2 p0 = __floats2half2_rn(D[nt][0], D[nt][1]);
            const __half2 p1 = __floats2half2_rn(D[nt][2], D[nt][3]);
            *(__half2*)&g_vox16[(size_t)v * 32 + 8 * nt + 2 * t]       = p0;
            *(__half2*)&g_vox16[(size_t)(v + 8) * 32 + 8 * nt + 2 * t] = p1;
        }
    }
}

// ---------------------------------------------------------------------------
// Fused gather + 3 MLP layers (fp16 mma, hi/lo split operands).
// R12 structure; gather loads pin voxel lines in L2 (evict_last policy);
// coord reads use evict_first policy; output stores are streaming (.cs).
// ---------------------------------------------------------------------------
#define SV_STRIDE 36   // uints per point: 16 hi + 16 lo + 4 pad

__global__ void __launch_bounds__(256, 3) fused_field_kernel(
    const float* __restrict__ coord,
    const float* __restrict__ b1g, const float* __restrict__ b2g,
    const float* __restrict__ b3g, const float* __restrict__ b4g,
    float* __restrict__ out)
{
    __shared__ uint4 swh[26 * 32];             // 13,312 B
    __shared__ float sb[128];                  //    512 B
    __shared__ uint32_t svu[256 * SV_STRIDE];  // 36,864 B

    const int tid = threadIdx.x;
    {
        for (int i = tid; i < 26 * 32; i += 256) swh[i] = g_whalf[i];
        if (tid < 32) {
            sb[tid]      = b1g[tid];
            sb[32 + tid] = b2g[tid];
            sb[64 + tid] = b3g[tid];
            sb[96 + tid] = (tid < 4) ? b4g[tid] : 0.0f;
        }
    }
    __syncthreads();

    const uint64_t poll = policy_evict_last();
    const uint64_t polf = policy_evict_first();

    const int warp  = tid >> 5;
    const int lane  = tid & 31;
    const int chunk = lane & 3;        // 16B slice (8 channels) of 32 fp16 channels
    const int psub  = lane >> 2;       // point-of-8 in round

    // --- Phase 1: pipelined warp-cooperative gather -> split fp16 in svu ---
    float cr[4][3];
#pragma unroll
    for (int s = 0; s < 4; s++) {
        const int q   = (warp << 5) + (s << 3) + psub;
        const int pid = blockIdx.x * 256 + q;
        cr[s][0] = ldg_hint_f32(&coord[pid * 3 + 0], polf);
        cr[s][1] = ldg_hint_f32(&coord[pid * 3 + 1], polf);
        cr[s][2] = ldg_hint_f32(&coord[pid * 3 + 2], polf);
    }

    float bb[8];
#pragma unroll
    for (int i = 0; i < 8; i++) bb[i] = sb[8 * chunk + i];   // b1 slice

#pragma unroll
    for (int s = 0; s < 4; s++) {
        const int q = (warp << 5) + (s << 3) + psub;

        const float fx = (cr[s][0] + 1.0f) * 64.0f - 0.5f;
        const float fy = (cr[s][1] + 1.0f) * 64.0f - 0.5f;
        const float fz = (cr[s][2] + 1.0f) * 64.0f - 0.5f;

        const float x0f = floorf(fx), y0f = floorf(fy), z0f = floorf(fz);
        const float tx = fx - x0f, ty = fy - y0f, tz = fz - z0f;
        const int x0 = (int)x0f, y0 = (int)y0f, z0 = (int)z0f;

        int   xs[2], ys[2], zs[2];
        float wx[2], wy[2], wz[2];
        xs[0] = max(x0, 0);        xs[1] = min(x0 + 1, RES - 1);
        ys[0] = max(y0, 0);        ys[1] = min(y0 + 1, RES - 1);
        zs[0] = max(z0, 0);        zs[1] = min(z0 + 1, RES - 1);
        wx[0] = (x0 >= 0)          ? (1.0f - tx) : 0.0f;
        wx[1] = (x0 + 1 <= RES - 1)? tx          : 0.0f;
        wy[0] = (y0 >= 0)          ? (1.0f - ty) : 0.0f;
        wy[1] = (y0 + 1 <= RES - 1)? ty          : 0.0f;
        wz[0] = (z0 >= 0)          ? (1.0f - tz) : 0.0f;
        wz[1] = (z0 + 1 <= RES - 1)? tz          : 0.0f;

        uint4 raw[8];
        float w8[8];
#pragma unroll
        for (int c = 0; c < 8; c++) {
            const int kx = c & 1, ky = (c >> 1) & 1, kz = c >> 2;
            const int vox = ((zs[kz] * RES + ys[ky]) * RES + xs[kx]);
            raw[c] = ldg_hint_v4u(((const uint4*)(g_vox16 + ((size_t)vox << 5))) + chunk, poll);
            w8[c]  = wz[kz] * wy[ky] * wx[kx];
        }

        float acc[8];
#pragma unroll
        for (int i = 0; i < 8; i++) acc[i] = bb[i];          // bias folded in
#pragma unroll
        for (int c = 0; c < 8; c++) {
            const __half2* h2 = (const __half2*)&raw[c];
            const float2 f0 = __half22float2(h2[0]);
            const float2 f1 = __half22float2(h2[1]);
            const float2 f2 = __half22float2(h2[2]);
            const float2 f3 = __half22float2(h2[3]);
            const float w = w8[c];
            acc[0] = fmaf(w, f0.x, acc[0]);  acc[1] = fmaf(w, f0.y, acc[1]);
            acc[2] = fmaf(w, f1.x, acc[2]);  acc[3] = fmaf(w, f1.y, acc[3]);
            acc[4] = fmaf(w, f2.x, acc[4]);  acc[5] = fmaf(w, f2.y, acc[5]);
            acc[6] = fmaf(w, f3.x, acc[6]);  acc[7] = fmaf(w, f3.y, acc[7]);
        }
        uint4 hi, lo;
        prelu_hilo2(acc[0], acc[1], hi.x, lo.x);
        prelu_hilo2(acc[2], acc[3], hi.y, lo.y);
        prelu_hilo2(acc[4], acc[5], hi.z, lo.z);
        prelu_hilo2(acc[6], acc[7], hi.w, lo.w);
        *(uint4*)&svu[q * SV_STRIDE + 4 * chunk]      = hi;  // relu(h1) hi
        *(uint4*)&svu[q * SV_STRIDE + 16 + 4 * chunk] = lo;  // relu(h1) lo
    }
    __syncwarp();

    // --- Phase 2: layers 2..4, one m-tile at a time ---
    const int gq = lane >> 2, t = lane & 3;

#pragma unroll
    for (int mt = 0; mt < 2; mt++) {
        const int q0 = warp * 32 + 16 * mt + gq;

        // layer 2: A = svu hi/lo, B = W2 frags 8..15, init b2
        float D[4][4];
#pragma unroll
        for (int nt = 0; nt < 4; nt++) {
            const float2 b2v = *(const float2*)&sb[32 + 8 * nt + 2 * t];
            D[nt][0] = b2v.x; D[nt][1] = b2v.y;
            D[nt][2] = b2v.x; D[nt][3] = b2v.y;
        }
#pragma unroll
        for (int ks = 0; ks < 2; ks++) {
            const uint32_t a0h = svu[q0 * SV_STRIDE + 8 * ks + t];
            const uint32_t a1h = svu[(q0 + 8) * SV_STRIDE + 8 * ks + t];
            const uint32_t a2h = svu[q0 * SV_STRIDE + 8 * ks + t + 4];
            const uint32_t a3h = svu[(q0 + 8) * SV_STRIDE + 8 * ks + t + 4];
            const uint32_t a0l = svu[q0 * SV_STRIDE + 16 + 8 * ks + t];
            const uint32_t a1l = svu[(q0 + 8) * SV_STRIDE + 16 + 8 * ks + t];
            const uint32_t a2l = svu[q0 * SV_STRIDE + 16 + 8 * ks + t + 4];
            const uint32_t a3l = svu[(q0 + 8) * SV_STRIDE + 16 + 8 * ks + t + 4];
#pragma unroll
            for (int nt = 0; nt < 4; nt++) {
                const uint4 B = swh[(8 + ks * 4 + nt) * 32 + lane];
                mma_f16(D[nt], a0h, a1h, a2h, a3h, B.x, B.y);
                mma_f16(D[nt], a0l, a1l, a2l, a3l, B.x, B.y);
                mma_f16(D[nt], a0h, a1h, a2h, a3h, B.z, B.w);
            }
        }

        // layer 3: A = relu(D) hi/lo, B = W3 frags 16..23, init b3
        float Dn[4][4];
#pragma unroll
        for (int nt = 0; nt < 4; nt++) {
            const float2 b3v = *(const float2*)&sb[64 + 8 * nt + 2 * t];
            Dn[nt][0] = b3v.x; Dn[nt][1] = b3v.y;
            Dn[nt][2] = b3v.x; Dn[nt][3] = b3v.y;
        }
#pragma unroll
        for (int ks = 0; ks < 2; ks++) {
            uint32_t a0h, a1h, a2h, a3h, a0l, a1l, a2l, a3l;
            prelu_hilo2(D[2 * ks][0],     D[2 * ks][1],     a0h, a0l);
            prelu_hilo2(D[2 * ks][2],     D[2 * ks][3],     a1h, a1l);
            prelu_hilo2(D[2 * ks + 1][0], D[2 * ks + 1][1], a2h, a2l);
            prelu_hilo2(D[2 * ks + 1][2], D[2 * ks + 1][3], a3h, a3l);
#pragma unroll
            for (int nt = 0; nt < 4; nt++) {
                const uint4 B = swh[(16 + ks * 4 + nt) * 32 + lane];
                mma_f16(Dn[nt], a0h, a1h, a2h, a3h, B.x, B.y);
                mma_f16(Dn[nt], a0l, a1l, a2l, a3l, B.x, B.y);
                mma_f16(Dn[nt], a0h, a1h, a2h, a3h, B.z, B.w);
            }
        }

        // layer 4: A = relu(Dn) hi/lo, B = W4 frags 24..25, init b4, no relu
        float O[4];
        {
            const float2 b4v = *(const float2*)&sb[96 + 2 * t];
            O[0] = b4v.x; O[1] = b4v.y;
            O[2] = b4v.x; O[3] = b4v.y;
        }
#pragma unroll
        for (int ks = 0; ks < 2; ks++) {
            uint32_t a0h, a1h, a2h, a3h, a0l, a1l, a2l, a3l;
            prelu_hilo2(Dn[2 * ks][0],     Dn[2 * ks][1],     a0h, a0l);
            prelu_hilo2(Dn[2 * ks][2],     Dn[2 * ks][3],     a1h, a1l);
            prelu_hilo2(Dn[2 * ks + 1][0], Dn[2 * ks + 1][1], a2h, a2l);
            prelu_hilo2(Dn[2 * ks + 1][2], Dn[2 * ks + 1][3], a3h, a3l);
            const uint4 B = swh[(24 + ks) * 32 + lane];
            mma_f16(O, a0h, a1h, a2h, a3h, B.x, B.y);
            mma_f16(O, a0l, a1l, a2l, a3l, B.x, B.y);
            mma_f16(O, a0h, a1h, a2h, a3h, B.z, B.w);
        }

        // store (streaming): rows gq, gq+8 of this m-tile, cols 2t,2t+1
        if (t < 2) {
            const int p0 = blockIdx.x * 256 + warp * 32 + 16 * mt + gq;
            stg_cs_v2f(&out[p0 * 4 + 2 * t],       O[0], O[1]);
            stg_cs_v2f(&out[(p0 + 8) * 4 + 2 * t], O[2], O[3]);
        }
    }
}

// ---------------------------------------------------------------------------
extern "C" void kernel_launch(void* const* d_in, const int* in_sizes, int n_in,
                              void* d_out, int out_size)
{
    const float* coord = (const float*)d_in[0];
    const float* grid  = (const float*)d_in[1];
    const float* w1 = (const float*)d_in[2];
    const float* b1 = (const float*)d_in[3];
    const float* w2 = (const float*)d_in[4];
    const float* b2 = (const float*)d_in[5];
    const float* w3 = (const float*)d_in[6];
    const float* b3 = (const float*)d_in[7];
    const float* w4 = (const float*)d_in[8];
    const float* b4 = (const float*)d_in[9];
    float* out = (float*)d_out;

    cudaFuncSetAttribute(fused_field_kernel,
                         cudaFuncAttributePreferredSharedMemoryCarveout, 62);

    prep_whalf_kernel<<<26, 32>>>(w1, w2, w3, w4);
    voxel_w1_kernel<<<NVOX / 256, 256>>>(grid);
    fused_field_kernel<<<NPTS / 256, 256>>>(coord, b1, b2, b3, b4, out);
}

// round 17
// speedup vs baseline: 1.0962x; 1.0320x over previous
#include <cuda_runtime.h>
#include <cuda_fp16.h>
#include <cstdint>

#define RES   128
#define FEAT  32
#define NVOX  (RES * RES * RES)           // 2,097,152 voxels
#define NPTS  (2048 * 1024)               // 2,097,152 points

// fp16 voxel tensor holding layer-1 pre-activations: vox[v*32+j] = (W1 @ g[:,v])[j]
__device__ __half g_vox16[(size_t)NVOX * FEAT];
// Split-fp16 B-fragments: W1 (0..7), W2 (8..15), W3 (16..23), W4 (24..25).
// Per lane: {hi_b0, hi_b1, lo_b0, lo_b1}.
__device__ uint4 g_whalf[26 * 32];

// ---------------------------------------------------------------------------
__device__ __forceinline__ void mma_f16(float d[4],
                                        uint32_t a0, uint32_t a1, uint32_t a2, uint32_t a3,
                                        uint32_t b0, uint32_t b1) {
    asm volatile("mma.sync.aligned.m16n8k16.row.col.f32.f16.f16.f32 "
                 "{%0,%1,%2,%3}, {%4,%5,%6,%7}, {%8,%9}, {%0,%1,%2,%3};"
                 : "+f"(d[0]), "+f"(d[1]), "+f"(d[2]), "+f"(d[3])
                 : "r"(a0), "r"(a1), "r"(a2), "r"(a3), "r"(b0), "r"(b1));
}

// L2 eviction hints — sm_103a ptxas rejects direct .L2::evict_* modifiers on
// anything narrower than 256-bit loads; createpolicy + cache_hint is width-free.
__device__ __forceinline__ uint64_t policy_evict_last() {
    uint64_t p;
    asm("createpolicy.fractional.L2::evict_last.b64 %0, 1.0;" : "=l"(p));
    return p;
}
__device__ __forceinline__ uint64_t policy_evict_first() {
    uint64_t p;
    asm("createpolicy.fractional.L2::evict_first.b64 %0, 1.0;" : "=l"(p));
    return p;
}
__device__ __forceinline__ uint4 ldg_hint_v4u(const void* p, uint64_t pol) {
    uint4 v;
    asm volatile("ld.global.nc.L2::cache_hint.v4.u32 {%0,%1,%2,%3}, [%4], %5;"
                 : "=r"(v.x), "=r"(v.y), "=r"(v.z), "=r"(v.w) : "l"(p), "l"(pol));
    return v;
}
__device__ __forceinline__ float ldg_hint_f32(const float* p, uint64_t pol) {
    float v;
    asm volatile("ld.global.nc.L2::cache_hint.f32 %0, [%1], %2;"
                 : "=f"(v) : "l"(p), "l"(pol));
    return v;
}
__device__ __forceinline__ float4 ldg_hint_v4f(const float* p, uint64_t pol) {
    float4 v;
    asm volatile("ld.global.nc.L2::cache_hint.v4.f32 {%0,%1,%2,%3}, [%4], %5;"
                 : "=f"(v.x), "=f"(v.y), "=f"(v.z), "=f"(v.w) : "l"(p), "l"(pol));
    return v;
}
__device__ __forceinline__ void stg_cs_v2f(float* p, float a, float b) {
    asm volatile("st.global.cs.v2.f32 [%0], {%1,%2};" :: "l"(p), "f"(a), "f"(b) : "memory");
}

// hi/lo fp16 split of a float pair (packed f16x2 each)
__device__ __forceinline__ void hilo2(float x, float y, uint32_t& hi, uint32_t& lo) {
    const __half2 h = __floats2half2_rn(x, y);
    hi = *(const uint32_t*)&h;
    const float2 hf = __half22float2(h);
    const __half2 l = __floats2half2_rn(x - hf.x, y - hf.y);
    lo = *(const uint32_t*)&l;
}

// relu, then hi/lo split
__device__ __forceinline__ void prelu_hilo2(float x, float y, uint32_t& hi, uint32_t& lo) {
    hilo2(fmaxf(x, 0.0f), fmaxf(y, 0.0f), hi, lo);
}

// ---------------------------------------------------------------------------
// Prep (single kernel): split-fp16 B-fragments for all layers, m16n8k16 order.
// ---------------------------------------------------------------------------
__global__ void prep_whalf_kernel(const float* __restrict__ w1, const float* __restrict__ w2,
                                  const float* __restrict__ w3, const float* __restrict__ w4) {
    const int f = blockIdx.x;        // 0..25
    const int lane = threadIdx.x;
    const int g = lane >> 2, t = lane & 3;
    float v0 = 0.f, v1 = 0.f, v2 = 0.f, v3 = 0.f;
    if (f < 24) {
        const float* W = (f < 8) ? w1 : (f < 16) ? w2 : w3;
        const int r = f & 7, ks = r >> 2, nt = r & 3;
        const int row = 8 * nt + g, k = 16 * ks;
        v0 = W[row * 32 + k + 2 * t];
        v1 = W[row * 32 + k + 2 * t + 1];
        v2 = W[row * 32 + k + 2 * t + 8];
        v3 = W[row * 32 + k + 2 * t + 9];
    } else {
        const int ks = f - 24;
        if (g < 4) {
            v0 = w4[g * 32 + 16 * ks + 2 * t];
            v1 = w4[g * 32 + 16 * ks + 2 * t + 1];
            v2 = w4[g * 32 + 16 * ks + 2 * t + 8];
            v3 = w4[g * 32 + 16 * ks + 2 * t + 9];
        }
    }
    uint4 u;
    hilo2(v0, v1, u.x, u.z);
    hilo2(v2, v3, u.y, u.w);
    g_whalf[f * 32 + lane] = u;
}

// ---------------------------------------------------------------------------
// Voxel transform: grid (C,D,H,W) -> fp16 (D*H*W, 32) of W1 @ v.
// Epilogue repacked: mma results staged in smem (stride-20-uint pad, the STS
// pattern (20*gq + 4*nt + t) mod 32 is a perfect bank permutation), then
// written out as 4 coalesced STG.128/thread instead of 16 scattered STG.32.
// ---------------------------------------------------------------------------
#define TC_STRIDE 260
#define VS_STRIDE 20   // uints per voxel in staging (16 used + 4 pad)
__global__ void __launch_bounds__(256, 4) voxel_w1_kernel(const float* __restrict__ g) {
    __shared__ union {
        float    tile[32 * TC_STRIDE];      // 33,280 B (input, c-major)
        uint32_t stage[256 * VS_STRIDE];    // 20,480 B (output staging)
    } sm;
    __shared__ uint4 swh1[8 * 32];          //  4,096 B (W1 frags)
    const int tid = threadIdx.x;
    const int v0 = blockIdx.x * 256;

    for (int i = tid; i < 8 * 32; i += 256) swh1[i] = g_whalf[i];

    const uint64_t polf = policy_evict_first();
#pragma unroll
    for (int i = 0; i < 8; i++) {
        const int idx = tid + i * 256;
        const int c = idx >> 6, v4 = idx & 63;
        const float4 val = ldg_hint_v4f(&g[(size_t)c * NVOX + v0 + v4 * 4], polf);
        *(float4*)&sm.tile[c * TC_STRIDE + v4 * 4] = val;
    }
    __syncthreads();

    const int warp = tid >> 5, lane = tid & 31;
    const int gq = lane >> 2, t = lane & 3;
    const int vb = warp * 32;

    // compute both m-tiles into registers first (input tile stays live)
    uint32_t P[2][4][2];   // [mt][nt][row-half]: packed half2 results
#pragma unroll
    for (int mt = 0; mt < 2; mt++) {
        const int r = vb + 16 * mt + gq;
        float D[4][4];
#pragma unroll
        for (int nt = 0; nt < 4; nt++)
#pragma unroll
            for (int i = 0; i < 4; i++) D[nt][i] = 0.0f;

#pragma unroll
        for (int ks = 0; ks < 2; ks++) {
            const int k = 16 * ks + 2 * t;
            uint32_t a0h, a0l, a1h, a1l, a2h, a2l, a3h, a3l;
            hilo2(sm.tile[k * TC_STRIDE + r],           sm.tile[(k + 1) * TC_STRIDE + r],     a0h, a0l);
            hilo2(sm.tile[k * TC_STRIDE + r + 8],       sm.tile[(k + 1) * TC_STRIDE + r + 8], a1h, a1l);
            hilo2(sm.tile[(k + 8) * TC_STRIDE + r],     sm.tile[(k + 9) * TC_STRIDE + r],     a2h, a2l);
            hilo2(sm.tile[(k + 8) * TC_STRIDE + r + 8], sm.tile[(k + 9) * TC_STRIDE + r + 8], a3h, a3l);
#pragma unroll
            for (int nt = 0; nt < 4; nt++) {
                const uint4 B = swh1[(ks * 4 + nt) * 32 + lane];
                mma_f16(D[nt], a0h, a1h, a2h, a3h, B.x, B.y);
                mma_f16(D[nt], a0l, a1l, a2l, a3l, B.x, B.y);
                mma_f16(D[nt], a0h, a1h, a2h, a3h, B.z, B.w);
            }
        }
#pragma unroll
        for (int nt = 0; nt < 4; nt++) {
            const __half2 p0 = __floats2half2_rn(D[nt][0], D[nt][1]);
            const __half2 p1 = __floats2half2_rn(D[nt][2], D[nt][3]);
            P[mt][nt][0] = *(const uint32_t*)&p0;
            P[mt][nt][1] = *(const uint32_t*)&p1;
        }
    }
    __syncthreads();   // done reading tile; stage overlays it

    // stage: voxel vloc, channel-pair word 4nt+t  (bank-perfect)
#pragma unroll
    for (int mt = 0; mt < 2; mt++) {
        const int r = vb + 16 * mt + gq;
#pragma unroll
        for (int nt = 0; nt < 4; nt++) {
            sm.stage[r * VS_STRIDE + 4 * nt + t]       = P[mt][nt][0];
            sm.stage[(r + 8) * VS_STRIDE + 4 * nt + t] = P[mt][nt][1];
        }
    }
    __syncthreads();

    // coalesced write-out: thread handles chunk id = tid + j*256;
    // vloc = id>>2, c4 = id&3 -> STG.128 at ((v0+vloc)*32 halves) + c4*16B.
#pragma unroll
    for (int j = 0; j < 4; j++) {
        const int id = tid + j * 256;
        const int vloc = id >> 2, c4 = id & 3;
        const uint32_t* s = &sm.stage[vloc * VS_STRIDE + 4 * c4];
        uint4 w;
        w.x = s[0]; w.y = s[1]; w.z = s[2]; w.w = s[3];
        *(((uint4*)(g_vox16 + ((size_t)(v0 + vloc) << 5))) + c4) = w;
    }
}

// ---------------------------------------------------------------------------
// Fused gather + 3 MLP layers (fp16 mma, hi/lo split operands).
// R16 structure (unchanged): voxel loads pinned via evict_last policy,
// coord reads evict_first, streaming output stores.
// ---------------------------------------------------------------------------
#define SV_STRIDE 36   // uints per point: 16 hi + 16 lo + 4 pad

__global__ void __launch_bounds__(256, 3) fused_field_kernel(
    const float* __restrict__ coord,
    const float* __restrict__ b1g, const float* __restrict__ b2g,
    const float* __restrict__ b3g, const float* __restrict__ b4g,
    float* __restrict__ out)
{
    __shared__ uint4 swh[26 * 32];             // 13,312 B
    __shared__ float sb[128];                  //    512 B
    __shared__ uint32_t svu[256 * SV_STRIDE];  // 36,864 B

    const int tid = threadIdx.x;
    {
        for (int i = tid; i < 26 * 32; i += 256) swh[i] = g_whalf[i];
        if (tid < 32) {
            sb[tid]      = b1g[tid];
            sb[32 + tid] = b2g[tid];
            sb[64 + tid] = b3g[tid];
            sb[96 + tid] = (tid < 4) ? b4g[tid] : 0.0f;
        }
    }
    __syncthreads();

    const uint64_t poll = policy_evict_last();
    const uint64_t polf = policy_evict_first();

    const int warp  = tid >> 5;
    const int lane  = tid & 31;
    const int chunk = lane & 3;        // 16B slice (8 channels) of 32 fp16 channels
    const int psub  = lane >> 2;       // point-of-8 in round

    // --- Phase 1: pipelined warp-cooperative gather -> split fp16 in svu ---
    float cr[4][3];
#pragma unroll
    for (int s = 0; s < 4; s++) {
        const int q   = (warp << 5) + (s << 3) + psub;
        const int pid = blockIdx.x * 256 + q;
        cr[s][0] = ldg_hint_f32(&coord[pid * 3 + 0], polf);
        cr[s][1] = ldg_hint_f32(&coord[pid * 3 + 1], polf);
        cr[s][2] = ldg_hint_f32(&coord[pid * 3 + 2], polf);
    }

    float bb[8];
#pragma unroll
    for (int i = 0; i < 8; i++) bb[i] = sb[8 * chunk + i];   // b1 slice

#pragma unroll
    for (int s = 0; s < 4; s++) {
        const int q = (warp << 5) + (s << 3) + psub;

        const float fx = (cr[s][0] + 1.0f) * 64.0f - 0.5f;
        const float fy = (cr[s][1] + 1.0f) * 64.0f - 0.5f;
        const float fz = (cr[s][2] + 1.0f) * 64.0f - 0.5f;

        const float x0f = floorf(fx), y0f = floorf(fy), z0f = floorf(fz);
        const float tx = fx - x0f, ty = fy - y0f, tz = fz - z0f;
        const int x0 = (int)x0f, y0 = (int)y0f, z0 = (int)z0f;

        int   xs[2], ys[2], zs[2];
        float wx[2], wy[2], wz[2];
        xs[0] = max(x0, 0);        xs[1] = min(x0 + 1, RES - 1);
        ys[0] = max(y0, 0);        ys[1] = min(y0 + 1, RES - 1);
        zs[0] = max(z0, 0);        zs[1] = min(z0 + 1, RES - 1);
        wx[0] = (x0 >= 0)          ? (1.0f - tx) : 0.0f;
        wx[1] = (x0 + 1 <= RES - 1)? tx          : 0.0f;
        wy[0] = (y0 >= 0)          ? (1.0f - ty) : 0.0f;
        wy[1] = (y0 + 1 <= RES - 1)? ty          : 0.0f;
        wz[0] = (z0 >= 0)          ? (1.0f - tz) : 0.0f;
        wz[1] = (z0 + 1 <= RES - 1)? tz          : 0.0f;

        uint4 raw[8];
        float w8[8];
#pragma unroll
        for (int c = 0; c < 8; c++) {
            const int kx = c & 1, ky = (c >> 1) & 1, kz = c >> 2;
            const int vox = ((zs[kz] * RES + ys[ky]) * RES + xs[kx]);
            raw[c] = ldg_hint_v4u(((const uint4*)(g_vox16 + ((size_t)vox << 5))) + chunk, poll);
            w8[c]  = wz[kz] * wy[ky] * wx[kx];
        }

        float acc[8];
#pragma unroll
        for (int i = 0; i < 8; i++) acc[i] = bb[i];          // bias folded in
#pragma unroll
        for (int c = 0; c < 8; c++) {
            const __half2* h2 = (const __half2*)&raw[c];
            const float2 f0 = __half22float2(h2[0]);
            const float2 f1 = __half22float2(h2[1]);
            const float2 f2 = __half22float2(h2[2]);
            const float2 f3 = __half22float2(h2[3]);
            const float w = w8[c];
            acc[0] = fmaf(w, f0.x, acc[0]);  acc[1] = fmaf(w, f0.y, acc[1]);
            acc[2] = fmaf(w, f1.x, acc[2]);  acc[3] = fmaf(w, f1.y, acc[3]);
            acc[4] = fmaf(w, f2.x, acc[4]);  acc[5] = fmaf(w, f2.y, acc[5]);
            acc[6] = fmaf(w, f3.x, acc[6]);  acc[7] = fmaf(w, f3.y, acc[7]);
        }
        uint4 hi, lo;
        prelu_hilo2(acc[0], acc[1], hi.x, lo.x);
        prelu_hilo2(acc[2], acc[3], hi.y, lo.y);
        prelu_hilo2(acc[4], acc[5], hi.z, lo.z);
        prelu_hilo2(acc[6], acc[7], hi.w, lo.w);
        *(uint4*)&svu[q * SV_STRIDE + 4 * chunk]      = hi;  // relu(h1) hi
        *(uint4*)&svu[q * SV_STRIDE + 16 + 4 * chunk] = lo;  // relu(h1) lo
    }
    __syncwarp();

    // --- Phase 2: layers 2..4, one m-tile at a time ---
    const int gq = lane >> 2, t = lane & 3;

#pragma unroll
    for (int mt = 0; mt < 2; mt++) {
        const int q0 = warp * 32 + 16 * mt + gq;

        // layer 2: A = svu hi/lo, B = W2 frags 8..15, init b2
        float D[4][4];
#pragma unroll
        for (int nt = 0; nt < 4; nt++) {
            const float2 b2v = *(const float2*)&sb[32 + 8 * nt + 2 * t];
            D[nt][0] = b2v.x; D[nt][1] = b2v.y;
            D[nt][2] = b2v.x; D[nt][3] = b2v.y;
        }
#pragma unroll
        for (int ks = 0; ks < 2; ks++) {
            const uint32_t a0h = svu[q0 * SV_STRIDE + 8 * ks + t];
            const uint32_t a1h = svu[(q0 + 8) * SV_STRIDE + 8 * ks + t];
            const uint32_t a2h = svu[q0 * SV_STRIDE + 8 * ks + t + 4];
            const uint32_t a3h = svu[(q0 + 8) * SV_STRIDE + 8 * ks + t + 4];
            const uint32_t a0l = svu[q0 * SV_STRIDE + 16 + 8 * ks + t];
            const uint32_t a1l = svu[(q0 + 8) * SV_STRIDE + 16 + 8 * ks + t];
            const uint32_t a2l = svu[q0 * SV_STRIDE + 16 + 8 * ks + t + 4];
            const uint32_t a3l = svu[(q0 + 8) * SV_STRIDE + 16 + 8 * ks + t + 4];
#pragma unroll
            for (int nt = 0; nt < 4; nt++) {
                const uint4 B = swh[(8 + ks * 4 + nt) * 32 + lane];
                mma_f16(D[nt], a0h, a1h, a2h, a3h, B.x, B.y);
                mma_f16(D[nt], a0l, a1l, a2l, a3l, B.x, B.y);
                mma_f16(D[nt], a0h, a1h, a2h, a3h, B.z, B.w);
            }
        }

        // layer 3: A = relu(D) hi/lo, B = W3 frags 16..23, init b3
        float Dn[4][4];
#pragma unroll
        for (int nt = 0; nt < 4; nt++) {
            const float2 b3v = *(const float2*)&sb[64 + 8 * nt + 2 * t];
            Dn[nt][0] = b3v.x; Dn[nt][1] = b3v.y;
            Dn[nt][2] = b3v.x; Dn[nt][3] = b3v.y;
        }
#pragma unroll
        for (int ks = 0; ks < 2; ks++) {
            uint32_t a0h, a1h, a2h, a3h, a0l, a1l, a2l, a3l;
            prelu_hilo2(D[2 * ks][0],     D[2 * ks][1],     a0h, a0l);
            prelu_hilo2(D[2 * ks][2],     D[2 * ks][3],     a1h, a1l);
            prelu_hilo2(D[2 * ks + 1][0], D[2 * ks + 1][1], a2h, a2l);
            prelu_hilo2(D[2 * ks + 1][2], D[2 * ks + 1][3], a3h, a3l);
#pragma unroll
            for (int nt = 0; nt < 4; nt++) {
                const uint4 B = swh[(16 + ks * 4 + nt) * 32 + lane];
                mma_f16(Dn[nt], a0h, a1h, a2h, a3h, B.x, B.y);
                mma_f16(Dn[nt], a0l, a1l, a2l, a3l, B.x, B.y);
                mma_f16(Dn[nt], a0h, a1h, a2h, a3h, B.z, B.w);
            }
        }

        // layer 4: A = relu(Dn) hi/lo, B = W4 frags 24..25, init b4, no relu
        float O[4];
        {
            const float2 b4v = *(const float2*)&sb[96 + 2 * t];
            O[0] = b4v.x; O[1] = b4v.y;
            O[2] = b4v.x; O[3] = b4v.y;
        }
#pragma unroll
        for (int ks = 0; ks < 2; ks++) {
            uint32_t a0h, a1h, a2h, a3h, a0l, a1l, a2l, a3l;
            prelu_hilo2(Dn[2 * ks][0],     Dn[2 * ks][1],     a0h, a0l);
            prelu_hilo2(Dn[2 * ks][2],     Dn[2 * ks][3],     a1h, a1l);
            prelu_hilo2(Dn[2 * ks + 1][0], Dn[2 * ks + 1][1], a2h, a2l);
            prelu_hilo2(Dn[2 * ks + 1][2], Dn[2 * ks + 1][3], a3h, a3l);
            const uint4 B = swh[(24 + ks) * 32 + lane];
            mma_f16(O, a0h, a1h, a2h, a3h, B.x, B.y);
            mma_f16(O, a0l, a1l, a2l, a3l, B.x, B.y);
            mma_f16(O, a0h, a1h, a2h, a3h, B.z, B.w);
        }

        // store (streaming): rows gq, gq+8 of this m-tile, cols 2t,2t+1
        if (t < 2) {
            const int p0 = blockIdx.x * 256 + warp * 32 + 16 * mt + gq;
            stg_cs_v2f(&out[p0 * 4 + 2 * t],       O[0], O[1]);
            stg_cs_v2f(&out[(p0 + 8) * 4 + 2 * t], O[2], O[3]);
        }
    }
}

// ---------------------------------------------------------------------------
extern "C" void kernel_launch(void* const* d_in, const int* in_sizes, int n_in,
                              void* d_out, int out_size)
{
    const float* coord = (const float*)d_in[0];
    const float* grid  = (const float*)d_in[1];
    const float* w1 = (const float*)d_in[2];
    const float* b1 = (const float*)d_in[3];
    const float* w2 = (const float*)d_in[4];
    const float* b2 = (const float*)d_in[5];
    const float* w3 = (const float*)d_in[6];
    const float* b3 = (const float*)d_in[7];
    const float* w4 = (const float*)d_in[8];
    const float* b4 = (const float*)d_in[9];
    float* out = (float*)d_out;

    cudaFuncSetAttribute(fused_field_kernel,
                         cudaFuncAttributePreferredSharedMemoryCarveout, 62);

    prep_whalf_kernel<<<26, 32>>>(w1, w2, w3, w4);
    voxel_w1_kernel<<<NVOX / 256, 256>>>(grid);
    fused_field_kernel<<<NPTS / 256, 256>>>(coord, b1, b2, b3, b4, out);
}